// round 3
// baseline (speedup 1.0000x reference)
#include <cuda_runtime.h>
#include <math.h>

#define DEV_DIM 192
#define PE_DIM  64
#define EMB     256
#define XDIM    256          // DEV_DIM + PE_DIM
#define OUTW    512          // 2*EMB
#define MAXM    262144
#define MAXB    1024

#define BM      32           // rows per block in gemm1
#define BK      8            // k-chunk
#define PITCH   36           // xsT row pitch (floats), keeps float4 alignment

// ------------------------- scratch (no allocations allowed) -------------------------
__device__ float g_sums[MAXB * EMB];
__device__ float g_maxs[MAXB * EMB];
__device__ float g_agg [MAXB * EMB];
__device__ float g_pos [MAXM];
__device__ int   g_bidx[MAXM];

// ------------------------- helpers -------------------------
__device__ __forceinline__ void atomicMaxF(float* addr, float v) {
    // mixed-sign float atomic max: positives via signed int max,
    // negatives via unsigned int min. init pattern must be 0xFF800000 (-inf).
    if (v >= 0.0f) atomicMax((int*)addr, __float_as_int(v));
    else           atomicMin((unsigned int*)addr, __float_as_uint(v));
}

// ------------------------- kernel 0: init segment accumulators -------------------------
__global__ void k_init(int B) {
    int i = blockIdx.x * blockDim.x + threadIdx.x;
    if (i < B * EMB) {
        g_sums[i] = 0.0f;
        ((unsigned int*)g_maxs)[i] = 0xFF800000u;   // -inf
    }
}

// ------------------------- kernel 1: batch_index + 1-based position -------------------------
// batch_index[j] = #{k in [1..B] : state_index[k] <= j}  (== searchsorted(state_index[1:], j, 'right'))
__global__ void k_bidx(const int* __restrict__ si, int M, int B) {
    int j = blockIdx.x * blockDim.x + threadIdx.x;
    if (j >= M) return;
    int lo = 1, hi = B + 1;
    while (lo < hi) {
        int mid = (lo + hi) >> 1;
        if (__ldg(si + mid) <= j) lo = mid + 1; else hi = mid;
    }
    int seg = lo - 1;
    g_bidx[j] = seg;
    g_pos[j]  = (float)(j - __ldg(si + seg) + 1);
}

// ------------------------- kernel 2: fused PE + GEMM1 + bias + LeakyReLU -------------------------
// out[:, 0:256] = leaky_relu(concat(states, PE(pos)) @ W1 + b1)
__global__ __launch_bounds__(256) void k_gemm1(
    const float* __restrict__ states, const float* __restrict__ W1,
    const float* __restrict__ b1, float* __restrict__ out, int M)
{
    __shared__ float xsT[XDIM * PITCH];     // x tile, transposed: xsT[k][row]
    __shared__ float Bs[BK * EMB];          // W1 k-chunk
    __shared__ float invf[PE_DIM / 2];

    const int tid  = threadIdx.x;
    const int row0 = blockIdx.x * BM;

    if (tid < PE_DIM / 2) {
        // match reference: exp(-log(10000)*(2i/d)) computed in fp32
        float lg = logf(10000.0f);
        invf[tid] = expf(-(lg * ((2.0f * (float)tid) / (float)PE_DIM)));
    }

    // stage states (32 rows x 192 cols) as float4 reads, transposed scalar writes
    for (int i = tid; i < BM * (DEV_DIM / 4); i += 256) {
        int r = i / (DEV_DIM / 4), q = i % (DEV_DIM / 4);
        int row = row0 + r;
        float4 v = (row < M) ? __ldg((const float4*)(states + (size_t)row * DEV_DIM) + q)
                             : make_float4(0.f, 0.f, 0.f, 0.f);
        int cb = q * 4;
        xsT[(cb + 0) * PITCH + r] = v.x;
        xsT[(cb + 1) * PITCH + r] = v.y;
        xsT[(cb + 2) * PITCH + r] = v.z;
        xsT[(cb + 3) * PITCH + r] = v.w;
    }
    __syncthreads();   // invf ready for PE phase

    // positional encoding: 32 rows x 32 freqs, sin/cos interleaved at cols 192..255
    for (int i = tid; i < BM * (PE_DIM / 2); i += 256) {
        int r = i >> 5, ii = i & 31;
        int row = row0 + r;
        float p = (row < M) ? g_pos[row] : 1.0f;
        float ang = p * invf[ii];
        // Cody-Waite reduction mod 2*pi (safe vs --use_fast_math sin)
        float kq = rintf(ang * 0.15915494309189535f);
        float rr = fmaf(kq, -6.28125f, ang);
        rr = fmaf(kq, -1.9353071795864769e-3f, rr);
        float s, c;
        __sincosf(rr, &s, &c);
        xsT[(DEV_DIM + 2 * ii) * PITCH + r]     = s;
        xsT[(DEV_DIM + 2 * ii + 1) * PITCH + r] = c;
    }

    float acc[4][8];
#pragma unroll
    for (int r = 0; r < 4; r++)
#pragma unroll
        for (int c = 0; c < 8; c++) acc[r][c] = 0.0f;

    const int lane = tid & 31;
    const int tr   = tid >> 5;
    const int colbase = lane * 8;     // 8 consecutive output cols per thread
    const int rbase   = tr * 4;       // 4 consecutive rows per thread

#pragma unroll 1
    for (int kb = 0; kb < XDIM / BK; kb++) {
        __syncthreads();   // kb==0: also orders xsT writes above
#pragma unroll
        for (int j = 0; j < BK; j++)
            Bs[j * EMB + tid] = __ldg(W1 + (size_t)(kb * BK + j) * EMB + tid);
        __syncthreads();
#pragma unroll
        for (int kk = 0; kk < BK; kk++) {
            int k = kb * BK + kk;
            float4 a  = *(const float4*)(xsT + k * PITCH + rbase);   // warp-broadcast
            float4 b0 = *(const float4*)(Bs + kk * EMB + colbase);
            float4 b1v= *(const float4*)(Bs + kk * EMB + colbase + 4);
            float av[4] = {a.x, a.y, a.z, a.w};
            float bv[8] = {b0.x, b0.y, b0.z, b0.w, b1v.x, b1v.y, b1v.z, b1v.w};
#pragma unroll
            for (int r = 0; r < 4; r++)
#pragma unroll
                for (int c = 0; c < 8; c++)
                    acc[r][c] = fmaf(av[r], bv[c], acc[r][c]);
        }
    }

    float4 bb0 = __ldg((const float4*)(b1 + colbase));
    float4 bb1 = __ldg((const float4*)(b1 + colbase + 4));
    float bias[8] = {bb0.x, bb0.y, bb0.z, bb0.w, bb1.x, bb1.y, bb1.z, bb1.w};

#pragma unroll
    for (int r = 0; r < 4; r++) {
        int row = row0 + rbase + r;
        if (row < M) {
            float v[8];
#pragma unroll
            for (int c = 0; c < 8; c++) {
                float t = acc[r][c] + bias[c];
                v[c] = (t >= 0.0f) ? t : 0.01f * t;
            }
            float4* p = (float4*)(out + (size_t)row * OUTW + colbase);
            p[0] = make_float4(v[0], v[1], v[2], v[3]);
            p[1] = make_float4(v[4], v[5], v[6], v[7]);
        }
    }
}

// ------------------------- kernel 3: ragged segment sum + max over h -------------------------
// rows are contiguous per segment, so each block scans 256 consecutive rows and
// flushes once per segment boundary -> ~2 atomics per column per boundary.
__global__ __launch_bounds__(256) void k_segred(const float* __restrict__ out, int M) {
    int c    = threadIdx.x;                 // column 0..255
    int row0 = blockIdx.x * 256;
    int rows = min(256, M - row0);
    float sum = 0.0f, mx = __int_as_float(0xFF800000);  // -inf
    int cur = __ldg(&g_bidx[row0]);
    for (int r = 0; r < rows; r++) {
        int row = row0 + r;
        int seg = __ldg(&g_bidx[row]);      // uniform across block -> broadcast
        if (seg != cur) {
            atomicAdd(&g_sums[cur * EMB + c], sum);
            atomicMaxF(&g_maxs[cur * EMB + c], mx);
            sum = 0.0f; mx = __int_as_float(0xFF800000); cur = seg;
        }
        float v = __ldg(out + (size_t)row * OUTW + c);
        sum += v;
        mx = fmaxf(mx, v);
    }
    atomicAdd(&g_sums[cur * EMB + c], sum);
    atomicMaxF(&g_maxs[cur * EMB + c], mx);
}

// ------------------------- kernel 4: agg = leaky_relu(concat(mean,max) @ W2 + b2) -------------------------
__global__ __launch_bounds__(256) void k_mlp(const int* __restrict__ si,
                                             const float* __restrict__ W2,
                                             const float* __restrict__ b2) {
    __shared__ float vec[2 * EMB];
    int s = blockIdx.x, c = threadIdx.x;
    int cnt = __ldg(si + s + 1) - __ldg(si + s);
    float inv = (cnt > 0) ? (1.0f / (float)cnt) : 1.0f;   // mean = sum/max(cnt,1)
    vec[c]       = g_sums[s * EMB + c] * inv;
    vec[EMB + c] = (cnt > 0) ? g_maxs[s * EMB + c] : 0.0f;
    __syncthreads();
    float acc = __ldg(b2 + c);
#pragma unroll 8
    for (int k = 0; k < 2 * EMB; k++)
        acc = fmaf(vec[k], __ldg(W2 + (size_t)k * EMB + c), acc);
    acc = (acc >= 0.0f) ? acc : 0.01f * acc;
    g_agg[s * EMB + c] = acc;
}

// ------------------------- kernel 5: broadcast agg into out[:, 256:512] -------------------------
__global__ __launch_bounds__(256) void k_bcast(float* __restrict__ out, int M) {
    int idx = blockIdx.x * blockDim.x + threadIdx.x;
    int row = idx >> 6;                     // 64 float4 per row half
    int q   = idx & 63;
    if (row >= M) return;
    int seg = __ldg(&g_bidx[row]);
    float4 v = __ldg((const float4*)(g_agg + (size_t)seg * EMB) + q);
    *((float4*)(out + (size_t)row * OUTW + EMB) + q) = v;
}

// ------------------------- kernel 6 (optional): second tuple output (batch_index) -------------------------
__global__ void k_tail(float* __restrict__ out, size_t off, int M) {
    int j = blockIdx.x * blockDim.x + threadIdx.x;
    if (j < M) out[off + j] = (float)g_bidx[j];
}

// ------------------------- launch -------------------------
extern "C" void kernel_launch(void* const* d_in, const int* in_sizes, int n_in,
                              void* d_out, int out_size) {
    const float* states = (const float*)d_in[0];
    const int*   si     = (const int*)  d_in[1];
    const float* W1     = (const float*)d_in[2];
    const float* b1     = (const float*)d_in[3];
    const float* W2     = (const float*)d_in[4];
    const float* b2     = (const float*)d_in[5];
    float* out = (float*)d_out;

    int M = in_sizes[0] / DEV_DIM;
    int B = in_sizes[1] - 1;
    if (M > MAXM) M = MAXM;
    if (B > MAXB) B = MAXB;

    k_init  <<<(B * EMB + 255) / 256, 256>>>(B);
    k_bidx  <<<(M + 255) / 256, 256>>>(si, M, B);
    k_gemm1 <<<(M + BM - 1) / BM, 256>>>(states, W1, b1, out, M);
    k_segred<<<(M + 255) / 256, 256>>>(out, M);
    k_mlp   <<<B, 256>>>(si, W2, b2);
    k_bcast <<<(M * 64 + 255) / 256, 256>>>(out, M);

    long long need = (long long)M * OUTW + (long long)M;
    if ((long long)out_size >= need)
        k_tail<<<(M + 255) / 256, 256>>>(out, (size_t)M * OUTW, M);
}

// round 5
// speedup vs baseline: 2.5464x; 2.5464x over previous
#include <cuda_runtime.h>
#include <cuda_bf16.h>
#include <math.h>

#define DEV_DIM 192
#define PE_DIM  64
#define EMB     256
#define XDIM    256          // K of GEMM1
#define OUTW    512
#define MAXM    262144
#define MAXB    1024

// ===================== scratch (no allocations allowed) =====================
__device__ float g_sums[MAXB * EMB];
__device__ float g_maxs[MAXB * EMB];
__device__ float g_agg [MAXB * EMB];
__device__ float g_pos [MAXM];
__device__ int   g_bidx[MAXM];
__device__ __nv_bfloat16 g_wt_hi[EMB * XDIM];   // W1^T hi  [n][k]
__device__ __nv_bfloat16 g_wt_lo[EMB * XDIM];   // W1^T lo  [n][k]

// ===================== helpers =====================
__device__ __forceinline__ unsigned smem_u32(const void* p) {
    unsigned a;
    asm("{ .reg .u64 t; cvta.to.shared.u64 t, %1; cvt.u32.u64 %0, t; }" : "=r"(a) : "l"(p));
    return a;
}
__device__ __forceinline__ void cp_async16(unsigned dst, const void* src) {
    asm volatile("cp.async.cg.shared.global [%0], [%1], 16;" :: "r"(dst), "l"(src));
}
#define CP_ASYNC_COMMIT()   asm volatile("cp.async.commit_group;" ::: "memory")
#define CP_ASYNC_WAIT_ALL() asm volatile("cp.async.wait_group 0;" ::: "memory")

__device__ __forceinline__ void mma_bf16(float* d, const unsigned* a, const unsigned* b) {
    asm volatile(
        "mma.sync.aligned.m16n8k16.row.col.f32.bf16.bf16.f32 "
        "{%0,%1,%2,%3}, {%4,%5,%6,%7}, {%8,%9}, {%0,%1,%2,%3};"
        : "+f"(d[0]), "+f"(d[1]), "+f"(d[2]), "+f"(d[3])
        : "r"(a[0]), "r"(a[1]), "r"(a[2]), "r"(a[3]), "r"(b[0]), "r"(b[1]));
}

__device__ __forceinline__ void atomicMaxF(float* addr, float v) {
    if (v >= 0.0f) atomicMax((int*)addr, __float_as_int(v));
    else           atomicMin((unsigned int*)addr, __float_as_uint(v));
}
__device__ __forceinline__ unsigned packbf2(float v0, float v1, float* r0, float* r1) {
    __nv_bfloat16 h0 = __float2bfloat16_rn(v0);
    __nv_bfloat16 h1 = __float2bfloat16_rn(v1);
    *r0 = v0 - __bfloat162float(h0);
    *r1 = v1 - __bfloat162float(h1);
    return ((unsigned)__bfloat16_as_ushort(h1) << 16) | (unsigned)__bfloat16_as_ushort(h0);
}
__device__ __forceinline__ unsigned packbf2_only(float v0, float v1) {
    return ((unsigned)__bfloat16_as_ushort(__float2bfloat16_rn(v1)) << 16)
         | (unsigned)__bfloat16_as_ushort(__float2bfloat16_rn(v0));
}

// ===================== kernel 0: init segment accumulators =====================
__global__ void k_init(int B) {
    int i = blockIdx.x * blockDim.x + threadIdx.x;
    if (i < B * EMB) {
        g_sums[i] = 0.0f;
        ((unsigned int*)g_maxs)[i] = 0xFF800000u;   // -inf
    }
}

// ===================== kernel 1: batch_index + 1-based position =====================
__global__ void k_bidx(const int* __restrict__ si, int M, int B) {
    int j = blockIdx.x * blockDim.x + threadIdx.x;
    if (j >= M) return;
    int lo = 1, hi = B + 1;
    while (lo < hi) {
        int mid = (lo + hi) >> 1;
        if (__ldg(si + mid) <= j) lo = mid + 1; else hi = mid;
    }
    int seg = lo - 1;
    g_bidx[j] = seg;
    g_pos[j]  = (float)(j - __ldg(si + seg) + 1);
}

// ===================== kernel 1b: W1 -> transposed bf16 hi/lo =====================
__global__ void k_prep(const float* __restrict__ W1) {
    int n = blockIdx.x;           // output col 0..255
    int k = threadIdx.x;          // k 0..255
    float w = __ldg(W1 + (size_t)k * EMB + n);
    __nv_bfloat16 h = __float2bfloat16_rn(w);
    g_wt_hi[n * XDIM + k] = h;
    g_wt_lo[n * XDIM + k] = __float2bfloat16_rn(w - __bfloat162float(h));
}

// ===================== kernel 2: bf16x3 HMMA GEMM1 (fused PE + bias + LeakyReLU) =====================
// CTA: 128 rows x 128 cols; K=256 in 8 chunks of 32, double buffered.
// 8 warps: warp_m = wid>>2 (2 x 64 rows), warp_n = wid&3 (4 x 32 cols).
#define KC     32
#define NCHK   8
#define PA     40                      // smem pitch in bf16 elems (80 B, 16B-aligned)
#define ABUF   10240                   // 128 * 40 * 2 bytes
#define OFF_BIAS 0
#define OFF_INVF 512
#define OFF_A    640                   // AH0,AL0,AH1,AL1
#define OFF_B    41600                 // BH0,BL0,BH1,BL1
#define SMEM_G1  82560

__device__ __forceinline__ void stage_B(unsigned sb, int cb, int ck, int buf) {
    int tid = threadIdx.x;
    unsigned bh = sb + OFF_B + buf * (2 * ABUF);
    unsigned bl = bh + ABUF;
    const char* srcH = (const char*)(g_wt_hi + (size_t)cb * 128 * XDIM + ck * KC);
    const char* srcL = (const char*)(g_wt_lo + (size_t)cb * 128 * XDIM + ck * KC);
    for (int i = tid; i < 512; i += 256) {
        int n = i >> 2, s = i & 3;
        unsigned d = (unsigned)(n * (PA * 2) + s * 16);
        cp_async16(bh + d, srcH + (size_t)n * (XDIM * 2) + s * 16);
        cp_async16(bl + d, srcL + (size_t)n * (XDIM * 2) + s * 16);
    }
}

__device__ __forceinline__ void load_A_vals(const float* __restrict__ states,
                                            float pos, const float* sinvf,
                                            int grow, int valid, int ck, float* v) {
    int kh = (threadIdx.x & 1) * 16;
    int kbase = ck * KC + kh;
    if (kbase < DEV_DIM) {
        if (valid) {
            const float4* p = (const float4*)(states + (size_t)grow * DEV_DIM + kbase);
#pragma unroll
            for (int q = 0; q < 4; q++) {
                float4 x = __ldg(p + q);
                v[q * 4 + 0] = x.x; v[q * 4 + 1] = x.y;
                v[q * 4 + 2] = x.z; v[q * 4 + 3] = x.w;
            }
        } else {
#pragma unroll
            for (int e = 0; e < 16; e++) v[e] = 0.0f;
        }
    } else {
        int c0 = kbase - DEV_DIM;       // 0..48, even
#pragma unroll
        for (int f = 0; f < 8; f++) {
            float ang = pos * sinvf[(c0 >> 1) + f];
            // Cody-Waite mod 2*pi (safe vs fast-math sin)
            float kq = rintf(ang * 0.15915494309189535f);
            float rr = fmaf(kq, -6.28125f, ang);
            rr = fmaf(kq, -1.9353071795864769e-3f, rr);
            float s, c;
            __sincosf(rr, &s, &c);
            v[2 * f] = s; v[2 * f + 1] = c;
        }
    }
}

__device__ __forceinline__ void store_A(char* smem, int buf, const float* v) {
    int arow = threadIdx.x >> 1;
    int kh   = (threadIdx.x & 1) * 16;
    unsigned hi[8], lo[8];
#pragma unroll
    for (int q = 0; q < 8; q++) {
        float r0, r1;
        hi[q] = packbf2(v[2 * q], v[2 * q + 1], &r0, &r1);
        lo[q] = packbf2_only(r0, r1);
    }
    char* ah = smem + OFF_A + buf * (2 * ABUF) + arow * (PA * 2) + kh * 2;
    char* al = ah + ABUF;
    ((uint4*)ah)[0] = make_uint4(hi[0], hi[1], hi[2], hi[3]);
    ((uint4*)ah)[1] = make_uint4(hi[4], hi[5], hi[6], hi[7]);
    ((uint4*)al)[0] = make_uint4(lo[0], lo[1], lo[2], lo[3]);
    ((uint4*)al)[1] = make_uint4(lo[4], lo[5], lo[6], lo[7]);
}

__global__ __launch_bounds__(256, 1) void k_gemm1_mma(
    const float* __restrict__ states, const float* __restrict__ b1,
    float* __restrict__ out, int M)
{
    extern __shared__ char smem[];
    const unsigned sb = smem_u32(smem);
    const int tid  = threadIdx.x;
    const int wid  = tid >> 5;
    const int lane = tid & 31;
    const int g    = lane >> 2;
    const int tg   = lane & 3;
    const int wm   = wid >> 2;       // 0..1
    const int wn   = wid & 3;        // 0..3
    const int row0 = blockIdx.x * 128;
    const int cb   = blockIdx.y;     // n-half 0..1

    float* sbias = (float*)(smem + OFF_BIAS);
    float* sinvf = (float*)(smem + OFF_INVF);

    if (tid < 128) sbias[tid] = __ldg(b1 + cb * 128 + tid);
    if (tid < 32) {
        float lg = logf(10000.0f);
        sinvf[tid] = expf(-(lg * ((2.0f * (float)tid) / (float)PE_DIM)));
    }
    __syncthreads();   // sinvf/sbias visible

    const int arow  = tid >> 1;
    const int grow  = row0 + arow;
    const int valid = (grow < M);
    const float pos = valid ? __ldg(&g_pos[grow]) : 1.0f;

    // ---- prologue: chunk 0 ----
    stage_B(sb, cb, 0, 0);
    CP_ASYNC_COMMIT();
    {
        float v[16];
        load_A_vals(states, pos, sinvf, grow, valid, 0, v);
        store_A(smem, 0, v);
    }
    CP_ASYNC_WAIT_ALL();
    __syncthreads();

    float acc[4][4][4];
#pragma unroll
    for (int i = 0; i < 4; i++)
#pragma unroll
        for (int j = 0; j < 4; j++)
#pragma unroll
            for (int e = 0; e < 4; e++) acc[i][j][e] = 0.0f;

#pragma unroll 1
    for (int c = 0; c < NCHK; c++) {
        const int buf = c & 1;
        float vnext[16];
        const bool more = (c < NCHK - 1);
        if (more) {
            stage_B(sb, cb, c + 1, buf ^ 1);
            CP_ASYNC_COMMIT();
            load_A_vals(states, pos, sinvf, grow, valid, c + 1, vnext);
        }

        const __nv_bfloat16* AH = (const __nv_bfloat16*)(smem + OFF_A + buf * (2 * ABUF));
        const __nv_bfloat16* AL = AH + ABUF / 2;
        const __nv_bfloat16* BH = (const __nv_bfloat16*)(smem + OFF_B + buf * (2 * ABUF));
        const __nv_bfloat16* BL = BH + ABUF / 2;

#pragma unroll
        for (int ks = 0; ks < 2; ks++) {
            const int k0 = ks * 16;
            unsigned ah[4][4], al[4][4], bh[4][2], bl[4][2];
#pragma unroll
            for (int i = 0; i < 4; i++) {
                int r0 = (wm * 64 + i * 16 + g) * PA + k0 + tg * 2;
                int r1 = r0 + 8 * PA;
                ah[i][0] = *(const unsigned*)(AH + r0);
                ah[i][1] = *(const unsigned*)(AH + r1);
                ah[i][2] = *(const unsigned*)(AH + r0 + 8);
                ah[i][3] = *(const unsigned*)(AH + r1 + 8);
                al[i][0] = *(const unsigned*)(AL + r0);
                al[i][1] = *(const unsigned*)(AL + r1);
                al[i][2] = *(const unsigned*)(AL + r0 + 8);
                al[i][3] = *(const unsigned*)(AL + r1 + 8);
            }
#pragma unroll
            for (int j = 0; j < 4; j++) {
                int nb = (wn * 32 + j * 8 + g) * PA + k0 + tg * 2;
                bh[j][0] = *(const unsigned*)(BH + nb);
                bh[j][1] = *(const unsigned*)(BH + nb + 8);
                bl[j][0] = *(const unsigned*)(BL + nb);
                bl[j][1] = *(const unsigned*)(BL + nb + 8);
            }
#pragma unroll
            for (int i = 0; i < 4; i++)
#pragma unroll
                for (int j = 0; j < 4; j++) mma_bf16(acc[i][j], ah[i], bh[j]);
#pragma unroll
            for (int i = 0; i < 4; i++)
#pragma unroll
                for (int j = 0; j < 4; j++) mma_bf16(acc[i][j], ah[i], bl[j]);
#pragma unroll
            for (int i = 0; i < 4; i++)
#pragma unroll
                for (int j = 0; j < 4; j++) mma_bf16(acc[i][j], al[i], bh[j]);
        }

        if (more) {
            store_A(smem, buf ^ 1, vnext);
            CP_ASYNC_WAIT_ALL();
            __syncthreads();
        }
    }

    // ---- epilogue: bias + LeakyReLU, store out[:, cb*128 .. +128) ----
#pragma unroll
    for (int i = 0; i < 4; i++) {
        int ra = row0 + wm * 64 + i * 16 + g;
#pragma unroll
        for (int h = 0; h < 2; h++) {
            int row = ra + h * 8;
            if (row < M) {
                float* op = out + (size_t)row * OUTW + cb * 128 + wn * 32;
#pragma unroll
                for (int j = 0; j < 4; j++) {
                    int ccol = j * 8 + tg * 2;
                    float x0 = acc[i][j][h * 2 + 0] + sbias[wn * 32 + ccol];
                    float x1 = acc[i][j][h * 2 + 1] + sbias[wn * 32 + ccol + 1];
                    x0 = (x0 >= 0.0f) ? x0 : 0.01f * x0;
                    x1 = (x1 >= 0.0f) ? x1 : 0.01f * x1;
                    *(float2*)(op + ccol) = make_float2(x0, x1);
                }
            }
        }
    }
}

// ===================== kernel 3: ragged segment sum + max (prefetched) =====================
__global__ __launch_bounds__(256) void k_segred(const float* __restrict__ out, int M) {
    __shared__ int sseg[256];
    int c = threadIdx.x;
    int row0 = blockIdx.x * 256;
    int rows = min(256, M - row0);
    sseg[c] = __ldg(&g_bidx[row0 + min(c, rows - 1)]);
    __syncthreads();
    const float* p = out + (size_t)row0 * OUTW + c;
    float v[8];
#pragma unroll
    for (int i = 0; i < 8; i++)
        v[i] = (i < rows) ? __ldg(p + (size_t)i * OUTW) : 0.0f;
    float sum = 0.0f, mx = __int_as_float(0xFF800000);
    int cur = sseg[0];
#pragma unroll 8
    for (int r = 0; r < 256; r++) {
        if (r >= rows) break;
        float val = v[r & 7];
        if (r + 8 < rows) v[r & 7] = __ldg(p + (size_t)(r + 8) * OUTW);
        int seg = sseg[r];
        if (seg != cur) {
            atomicAdd(&g_sums[cur * EMB + c], sum);
            atomicMaxF(&g_maxs[cur * EMB + c], mx);
            sum = 0.0f; mx = __int_as_float(0xFF800000); cur = seg;
        }
        sum += val;
        mx = fmaxf(mx, val);
    }
    atomicAdd(&g_sums[cur * EMB + c], sum);
    atomicMaxF(&g_maxs[cur * EMB + c], mx);
}

// ===================== kernel 4: agg = leaky(concat(mean,max) @ W2 + b2) =====================
__global__ __launch_bounds__(256) void k_mlp(const int* __restrict__ si,
                                             const float* __restrict__ W2,
                                             const float* __restrict__ b2) {
    __shared__ float vec[2 * EMB];
    __shared__ float par[4][EMB];
    int s = blockIdx.x, t = threadIdx.x;
    int cnt = __ldg(si + s + 1) - __ldg(si + s);
    float inv = (cnt > 0) ? (1.0f / (float)cnt) : 1.0f;
    vec[t]       = g_sums[s * EMB + t] * inv;
    vec[EMB + t] = (cnt > 0) ? g_maxs[s * EMB + t] : 0.0f;
    __syncthreads();
    int tq = t >> 6;              // k-split 0..3
    int tc = (t & 63) * 4;        // 4 consecutive cols
    float a0 = 0.f, a1 = 0.f, a2 = 0.f, a3 = 0.f;
#pragma unroll 4
    for (int k = tq * 128; k < tq * 128 + 128; k++) {
        float vk = vec[k];
        float4 w = __ldg((const float4*)(W2 + (size_t)k * EMB + tc));
        a0 = fmaf(vk, w.x, a0); a1 = fmaf(vk, w.y, a1);
        a2 = fmaf(vk, w.z, a2); a3 = fmaf(vk, w.w, a3);
    }
    par[tq][tc] = a0; par[tq][tc + 1] = a1; par[tq][tc + 2] = a2; par[tq][tc + 3] = a3;
    __syncthreads();
    if (tq == 0) {
#pragma unroll
        for (int e = 0; e < 4; e++) {
            int cc = tc + e;
            float acc = par[0][cc] + par[1][cc] + par[2][cc] + par[3][cc] + __ldg(b2 + cc);
            acc = (acc >= 0.0f) ? acc : 0.01f * acc;
            g_agg[s * EMB + cc] = acc;
        }
    }
}

// ===================== kernel 5: broadcast agg into out[:, 256:512] =====================
__global__ __launch_bounds__(256) void k_bcast(float* __restrict__ out, int M) {
    int idx = blockIdx.x * blockDim.x + threadIdx.x;
    int row = idx >> 6;
    int q   = idx & 63;
    if (row >= M) return;
    int seg = __ldg(&g_bidx[row]);
    float4 v = __ldg((const float4*)(g_agg + (size_t)seg * EMB) + q);
    *((float4*)(out + (size_t)row * OUTW + EMB) + q) = v;
}

// ===================== kernel 6 (optional): second tuple output (batch_index) =====================
__global__ void k_tail(float* __restrict__ out, size_t off, int M) {
    int j = blockIdx.x * blockDim.x + threadIdx.x;
    if (j < M) out[off + j] = (float)g_bidx[j];
}

// ===================== launch =====================
extern "C" void kernel_launch(void* const* d_in, const int* in_sizes, int n_in,
                              void* d_out, int out_size) {
    const float* states = (const float*)d_in[0];
    const int*   si     = (const int*)  d_in[1];
    const float* W1     = (const float*)d_in[2];
    const float* b1     = (const float*)d_in[3];
    const float* W2     = (const float*)d_in[4];
    const float* b2     = (const float*)d_in[5];
    float* out = (float*)d_out;

    int M = in_sizes[0] / DEV_DIM;
    int B = in_sizes[1] - 1;
    if (M > MAXM) M = MAXM;
    if (B > MAXB) B = MAXB;

    cudaFuncSetAttribute(k_gemm1_mma, cudaFuncAttributeMaxDynamicSharedMemorySize, SMEM_G1);

    k_init     <<<(B * EMB + 255) / 256, 256>>>(B);
    k_bidx     <<<(M + 255) / 256, 256>>>(si, M, B);
    k_prep     <<<EMB, XDIM>>>(W1);
    dim3 grid1((M + 127) / 128, 2);
    k_gemm1_mma<<<grid1, 256, SMEM_G1>>>(states, b1, out, M);
    k_segred   <<<(M + 255) / 256, 256>>>(out, M);
    k_mlp      <<<B, 256>>>(si, W2, b2);
    k_bcast    <<<(M * 64 + 255) / 256, 256>>>(out, M);

    long long need = (long long)M * OUTW + (long long)M;
    if ((long long)out_size >= need)
        k_tail<<<(M + 255) / 256, 256>>>(out, (size_t)M * OUTW, M);
}

// round 6
// speedup vs baseline: 2.8092x; 1.1032x over previous
#include <cuda_runtime.h>
#include <cuda_bf16.h>
#include <math.h>

#define DEV_DIM 192
#define PE_DIM  64
#define EMB     256
#define XDIM    256          // K of GEMM1
#define OUTW    512
#define MAXM    262144
#define MAXB    1024

// ===================== scratch (no allocations allowed) =====================
__device__ float g_sums[MAXB * EMB];
__device__ float g_maxs[MAXB * EMB];
__device__ float g_agg [MAXB * EMB];
__device__ float g_pos [MAXM];
__device__ int   g_bidx[MAXM];
__device__ __nv_bfloat16 g_wt_hi[EMB * XDIM];   // W1^T hi  [n][k]
__device__ __nv_bfloat16 g_wt_lo[EMB * XDIM];   // W1^T lo  [n][k]

// ===================== helpers =====================
__device__ __forceinline__ unsigned smem_u32(const void* p) {
    unsigned a;
    asm("{ .reg .u64 t; cvta.to.shared.u64 t, %1; cvt.u32.u64 %0, t; }" : "=r"(a) : "l"(p));
    return a;
}
__device__ __forceinline__ void cp_async16(unsigned dst, const void* src) {
    asm volatile("cp.async.cg.shared.global [%0], [%1], 16;" :: "r"(dst), "l"(src));
}
#define CP_ASYNC_COMMIT()   asm volatile("cp.async.commit_group;" ::: "memory")
#define CP_ASYNC_WAIT_ALL() asm volatile("cp.async.wait_group 0;" ::: "memory")

#define LDSM_X4(r0, r1, r2, r3, addr)                                          \
    asm volatile("ldmatrix.sync.aligned.m8n8.x4.shared.b16 {%0,%1,%2,%3}, [%4];" \
        : "=r"(r0), "=r"(r1), "=r"(r2), "=r"(r3) : "r"(addr))

__device__ __forceinline__ void mma_bf16(float* d, const unsigned* a, const unsigned* b) {
    asm volatile(
        "mma.sync.aligned.m16n8k16.row.col.f32.bf16.bf16.f32 "
        "{%0,%1,%2,%3}, {%4,%5,%6,%7}, {%8,%9}, {%0,%1,%2,%3};"
        : "+f"(d[0]), "+f"(d[1]), "+f"(d[2]), "+f"(d[3])
        : "r"(a[0]), "r"(a[1]), "r"(a[2]), "r"(a[3]), "r"(b[0]), "r"(b[1]));
}

__device__ __forceinline__ void atomicMaxF(float* addr, float v) {
    if (v >= 0.0f) atomicMax((int*)addr, __float_as_int(v));
    else           atomicMin((unsigned int*)addr, __float_as_uint(v));
}
__device__ __forceinline__ unsigned packbf2(float v0, float v1, float* r0, float* r1) {
    __nv_bfloat16 h0 = __float2bfloat16_rn(v0);
    __nv_bfloat16 h1 = __float2bfloat16_rn(v1);
    *r0 = v0 - __bfloat162float(h0);
    *r1 = v1 - __bfloat162float(h1);
    return ((unsigned)__bfloat16_as_ushort(h1) << 16) | (unsigned)__bfloat16_as_ushort(h0);
}
__device__ __forceinline__ unsigned packbf2_only(float v0, float v1) {
    return ((unsigned)__bfloat16_as_ushort(__float2bfloat16_rn(v1)) << 16)
         | (unsigned)__bfloat16_as_ushort(__float2bfloat16_rn(v0));
}

// ===================== kernel 0: init segment accumulators =====================
__global__ void k_init(int B) {
    int i = blockIdx.x * blockDim.x + threadIdx.x;
    if (i < B * EMB) {
        g_sums[i] = 0.0f;
        ((unsigned int*)g_maxs)[i] = 0xFF800000u;   // -inf
    }
}

// ===================== kernel 1: batch_index + 1-based position =====================
__global__ void k_bidx(const int* __restrict__ si, int M, int B) {
    int j = blockIdx.x * blockDim.x + threadIdx.x;
    if (j >= M) return;
    int lo = 1, hi = B + 1;
    while (lo < hi) {
        int mid = (lo + hi) >> 1;
        if (__ldg(si + mid) <= j) lo = mid + 1; else hi = mid;
    }
    int seg = lo - 1;
    g_bidx[j] = seg;
    g_pos[j]  = (float)(j - __ldg(si + seg) + 1);
}

// ===================== kernel 1b: W1 -> transposed bf16 hi/lo =====================
__global__ void k_prep(const float* __restrict__ W1) {
    int n = blockIdx.x;           // output col 0..255
    int k = threadIdx.x;          // k 0..255
    float w = __ldg(W1 + (size_t)k * EMB + n);
    __nv_bfloat16 h = __float2bfloat16_rn(w);
    g_wt_hi[n * XDIM + k] = h;
    g_wt_lo[n * XDIM + k] = __float2bfloat16_rn(w - __bfloat162float(h));
}

// ===================== kernel 2: bf16x3 HMMA GEMM1 via ldmatrix =====================
// CTA: 128 rows x 128 cols, 512 threads (16 warps, warp tile 32x32).
// K=256 in 8 chunks of 32, double buffered. Chunks 0-5: states, 6-7: PE.
#define KC     32
#define NCHK   8
#define PA     40                       // smem pitch in bf16 (80 B)
#define ABUF   10240                    // 128 * 40 * 2 bytes per matrix
#define A_TILE 1280                     // 16 * PA * 2 bytes (one 16-row tile)
#define OFF_BIAS 0
#define OFF_INVF 512
#define OFF_A    640                    // [buf][AH | AL]
#define OFF_B    41600                  // [buf][BH | BL]
#define SMEM_G1  82560
#define KSTEP_B  32                     // 16 k * 2 bytes

__device__ __forceinline__ void stage_B(unsigned sb, int cb, int ck, int buf) {
    int tid = threadIdx.x;
    unsigned bh = sb + OFF_B + buf * (2 * ABUF);
    unsigned bl = bh + ABUF;
    const char* srcH = (const char*)(g_wt_hi + (size_t)cb * 128 * XDIM + ck * KC);
    const char* srcL = (const char*)(g_wt_lo + (size_t)cb * 128 * XDIM + ck * KC);
    // per matrix: 128 n-rows * 4 x 16B segments = 512
    int n = tid >> 2, s = tid & 3;
    unsigned d = (unsigned)(n * (PA * 2) + s * 16);
    cp_async16(bh + d, srcH + (size_t)n * (XDIM * 2) + s * 16);
    cp_async16(bl + d, srcL + (size_t)n * (XDIM * 2) + s * 16);
}

__device__ __forceinline__ void load_A_vals(const float* __restrict__ states,
                                            float pos, const float* sinvf,
                                            int grow, int valid, int ck, float* v) {
    int kq = (threadIdx.x & 3) * 8;
    int kbase = ck * KC + kq;
    if (ck < 6) {                       // pure states
        if (valid) {
            const float4* p = (const float4*)(states + (size_t)grow * DEV_DIM + kbase);
            float4 x = __ldg(p);
            float4 y = __ldg(p + 1);
            v[0] = x.x; v[1] = x.y; v[2] = x.z; v[3] = x.w;
            v[4] = y.x; v[5] = y.y; v[6] = y.z; v[7] = y.w;
        } else {
#pragma unroll
            for (int e = 0; e < 8; e++) v[e] = 0.0f;
        }
    } else {                            // pure PE
        int c0 = kbase - DEV_DIM;       // 0..56, multiple of 8
#pragma unroll
        for (int f = 0; f < 4; f++) {
            float ang = pos * sinvf[(c0 >> 1) + f];
            float kq2 = rintf(ang * 0.15915494309189535f);
            float rr = fmaf(kq2, -6.28125f, ang);
            rr = fmaf(kq2, -1.9353071795864769e-3f, rr);
            float s, c;
            __sincosf(rr, &s, &c);
            v[2 * f] = s; v[2 * f + 1] = c;
        }
    }
}

__device__ __forceinline__ void store_A(char* smem, int buf, const float* v) {
    int arow = threadIdx.x >> 2;
    int kq   = (threadIdx.x & 3) * 8;
    unsigned hi[4], lo[4];
#pragma unroll
    for (int q = 0; q < 4; q++) {
        float r0, r1;
        hi[q] = packbf2(v[2 * q], v[2 * q + 1], &r0, &r1);
        lo[q] = packbf2_only(r0, r1);
    }
    char* ah = smem + OFF_A + buf * (2 * ABUF) + arow * (PA * 2) + kq * 2;
    char* al = ah + ABUF;
    *(uint4*)ah = make_uint4(hi[0], hi[1], hi[2], hi[3]);
    *(uint4*)al = make_uint4(lo[0], lo[1], lo[2], lo[3]);
}

__global__ __launch_bounds__(512, 1) void k_gemm1_mma(
    const float* __restrict__ states, const float* __restrict__ b1,
    float* __restrict__ out, int M)
{
    extern __shared__ char smem[];
    const unsigned sb = smem_u32(smem);
    const int tid  = threadIdx.x;
    const int wid  = tid >> 5;
    const int lane = tid & 31;
    const int g    = lane >> 2;
    const int tg   = lane & 3;
    const int wm   = wid >> 2;       // 0..3 (32 rows each)
    const int wn   = wid & 3;        // 0..3 (32 cols each)
    const int row0 = blockIdx.x * 128;
    const int cb   = blockIdx.y;     // n-half 0..1

    float* sbias = (float*)(smem + OFF_BIAS);
    float* sinvf = (float*)(smem + OFF_INVF);

    if (tid < 128) sbias[tid] = __ldg(b1 + cb * 128 + tid);
    if (tid < 32) {
        float lg = logf(10000.0f);
        sinvf[tid] = expf(-(lg * ((2.0f * (float)tid) / (float)PE_DIM)));
    }
    __syncthreads();

    const int arow  = tid >> 2;
    const int grow  = row0 + arow;
    const int valid = (grow < M);
    const float pos = valid ? __ldg(&g_pos[grow]) : 1.0f;

    // ldmatrix per-lane offsets
    const int g4 = lane >> 3;           // 0..3
    const int lr = lane & 7;
    const unsigned a_off = (unsigned)((wm * 32 + (g4 & 1) * 8 + lr) * (PA * 2)) + (g4 >> 1) * 16;
    const unsigned b_off = (unsigned)((wn * 32 + (g4 >> 1) * 8 + lr) * (PA * 2)) + (g4 & 1) * 16;

    // ---- prologue: chunk 0 ----
    stage_B(sb, cb, 0, 0);
    CP_ASYNC_COMMIT();
    {
        float v[8];
        load_A_vals(states, pos, sinvf, grow, valid, 0, v);
        store_A(smem, 0, v);
    }
    CP_ASYNC_WAIT_ALL();
    __syncthreads();

    float acc[2][4][4];
#pragma unroll
    for (int i = 0; i < 2; i++)
#pragma unroll
        for (int j = 0; j < 4; j++)
#pragma unroll
            for (int e = 0; e < 4; e++) acc[i][j][e] = 0.0f;

#pragma unroll 1
    for (int c = 0; c < NCHK; c++) {
        const int buf = c & 1;
        float vnext[8];
        const bool more = (c < NCHK - 1);
        if (more) {
            stage_B(sb, cb, c + 1, buf ^ 1);
            CP_ASYNC_COMMIT();
            load_A_vals(states, pos, sinvf, grow, valid, c + 1, vnext);
        }

        const unsigned sAH = sb + OFF_A + buf * (2 * ABUF);
        const unsigned sAL = sAH + ABUF;
        const unsigned sBH = sb + OFF_B + buf * (2 * ABUF);
        const unsigned sBL = sBH + ABUF;

#pragma unroll
        for (int ks = 0; ks < 2; ks++) {
            const unsigned kb = ks * KSTEP_B;
            unsigned ah[2][4], al[2][4], bh[4][2], bl[4][2];
#pragma unroll
            for (int i = 0; i < 2; i++) {
                LDSM_X4(ah[i][0], ah[i][1], ah[i][2], ah[i][3],
                        sAH + a_off + i * A_TILE + kb);
                LDSM_X4(al[i][0], al[i][1], al[i][2], al[i][3],
                        sAL + a_off + i * A_TILE + kb);
            }
#pragma unroll
            for (int jj = 0; jj < 2; jj++) {
                LDSM_X4(bh[2 * jj][0], bh[2 * jj][1], bh[2 * jj + 1][0], bh[2 * jj + 1][1],
                        sBH + b_off + jj * A_TILE + kb);
                LDSM_X4(bl[2 * jj][0], bl[2 * jj][1], bl[2 * jj + 1][0], bl[2 * jj + 1][1],
                        sBL + b_off + jj * A_TILE + kb);
            }
#pragma unroll
            for (int i = 0; i < 2; i++)
#pragma unroll
                for (int j = 0; j < 4; j++) mma_bf16(acc[i][j], ah[i], bh[j]);
#pragma unroll
            for (int i = 0; i < 2; i++)
#pragma unroll
                for (int j = 0; j < 4; j++) mma_bf16(acc[i][j], ah[i], bl[j]);
#pragma unroll
            for (int i = 0; i < 2; i++)
#pragma unroll
                for (int j = 0; j < 4; j++) mma_bf16(acc[i][j], al[i], bh[j]);
        }

        if (more) {
            store_A(smem, buf ^ 1, vnext);
            CP_ASYNC_WAIT_ALL();
            __syncthreads();
        }
    }

    // ---- epilogue: bias + LeakyReLU, store out[:, cb*128 .. +128) ----
#pragma unroll
    for (int i = 0; i < 2; i++) {
        int ra = row0 + wm * 32 + i * 16 + g;
#pragma unroll
        for (int h = 0; h < 2; h++) {
            int row = ra + h * 8;
            if (row < M) {
                float* op = out + (size_t)row * OUTW + cb * 128 + wn * 32;
#pragma unroll
                for (int j = 0; j < 4; j++) {
                    int ccol = j * 8 + tg * 2;
                    float x0 = acc[i][j][h * 2 + 0] + sbias[wn * 32 + ccol];
                    float x1 = acc[i][j][h * 2 + 1] + sbias[wn * 32 + ccol + 1];
                    x0 = (x0 >= 0.0f) ? x0 : 0.01f * x0;
                    x1 = (x1 >= 0.0f) ? x1 : 0.01f * x1;
                    *(float2*)(op + ccol) = make_float2(x0, x1);
                }
            }
        }
    }
}

// ===================== kernel 3: ragged segment sum + max (prefetched) =====================
__global__ __launch_bounds__(256) void k_segred(const float* __restrict__ out, int M) {
    __shared__ int sseg[256];
    int c = threadIdx.x;
    int row0 = blockIdx.x * 256;
    int rows = min(256, M - row0);
    sseg[c] = __ldg(&g_bidx[row0 + min(c, rows - 1)]);
    __syncthreads();
    const float* p = out + (size_t)row0 * OUTW + c;
    float v[8];
#pragma unroll
    for (int i = 0; i < 8; i++)
        v[i] = (i < rows) ? __ldg(p + (size_t)i * OUTW) : 0.0f;
    float sum = 0.0f, mx = __int_as_float(0xFF800000);
    int cur = sseg[0];
#pragma unroll 8
    for (int r = 0; r < 256; r++) {
        if (r >= rows) break;
        float val = v[r & 7];
        if (r + 8 < rows) v[r & 7] = __ldg(p + (size_t)(r + 8) * OUTW);
        int seg = sseg[r];
        if (seg != cur) {
            atomicAdd(&g_sums[cur * EMB + c], sum);
            atomicMaxF(&g_maxs[cur * EMB + c], mx);
            sum = 0.0f; mx = __int_as_float(0xFF800000); cur = seg;
        }
        sum += val;
        mx = fmaxf(mx, val);
    }
    atomicAdd(&g_sums[cur * EMB + c], sum);
    atomicMaxF(&g_maxs[cur * EMB + c], mx);
}

// ===================== kernel 4: agg = leaky(concat(mean,max) @ W2 + b2) =====================
__global__ __launch_bounds__(256) void k_mlp(const int* __restrict__ si,
                                             const float* __restrict__ W2,
                                             const float* __restrict__ b2) {
    __shared__ float vec[2 * EMB];
    __shared__ float par[4][EMB];
    int s = blockIdx.x, t = threadIdx.x;
    int cnt = __ldg(si + s + 1) - __ldg(si + s);
    float inv = (cnt > 0) ? (1.0f / (float)cnt) : 1.0f;
    vec[t]       = g_sums[s * EMB + t] * inv;
    vec[EMB + t] = (cnt > 0) ? g_maxs[s * EMB + t] : 0.0f;
    __syncthreads();
    int tq = t >> 6;
    int tc = (t & 63) * 4;
    float a0 = 0.f, a1 = 0.f, a2 = 0.f, a3 = 0.f;
#pragma unroll 4
    for (int k = tq * 128; k < tq * 128 + 128; k++) {
        float vk = vec[k];
        float4 w = __ldg((const float4*)(W2 + (size_t)k * EMB + tc));
        a0 = fmaf(vk, w.x, a0); a1 = fmaf(vk, w.y, a1);
        a2 = fmaf(vk, w.z, a2); a3 = fmaf(vk, w.w, a3);
    }
    par[tq][tc] = a0; par[tq][tc + 1] = a1; par[tq][tc + 2] = a2; par[tq][tc + 3] = a3;
    __syncthreads();
    if (tq == 0) {
#pragma unroll
        for (int e = 0; e < 4; e++) {
            int cc = tc + e;
            float acc = par[0][cc] + par[1][cc] + par[2][cc] + par[3][cc] + __ldg(b2 + cc);
            acc = (acc >= 0.0f) ? acc : 0.01f * acc;
            g_agg[s * EMB + cc] = acc;
        }
    }
}

// ===================== kernel 5: broadcast agg into out[:, 256:512] =====================
__global__ __launch_bounds__(256) void k_bcast(float* __restrict__ out, int M) {
    int idx = blockIdx.x * blockDim.x + threadIdx.x;
    int row = idx >> 6;
    int q   = idx & 63;
    if (row >= M) return;
    int seg = __ldg(&g_bidx[row]);
    float4 v = __ldg((const float4*)(g_agg + (size_t)seg * EMB) + q);
    *((float4*)(out + (size_t)row * OUTW + EMB) + q) = v;
}

// ===================== kernel 6 (optional): second tuple output (batch_index) =====================
__global__ void k_tail(float* __restrict__ out, size_t off, int M) {
    int j = blockIdx.x * blockDim.x + threadIdx.x;
    if (j < M) out[off + j] = (float)g_bidx[j];
}

// ===================== launch =====================
extern "C" void kernel_launch(void* const* d_in, const int* in_sizes, int n_in,
                              void* d_out, int out_size) {
    const float* states = (const float*)d_in[0];
    const int*   si     = (const int*)  d_in[1];
    const float* W1     = (const float*)d_in[2];
    const float* b1     = (const float*)d_in[3];
    const float* W2     = (const float*)d_in[4];
    const float* b2     = (const float*)d_in[5];
    float* out = (float*)d_out;

    int M = in_sizes[0] / DEV_DIM;
    int B = in_sizes[1] - 1;
    if (M > MAXM) M = MAXM;
    if (B > MAXB) B = MAXB;

    cudaFuncSetAttribute(k_gemm1_mma, cudaFuncAttributeMaxDynamicSharedMemorySize, SMEM_G1);

    k_init     <<<(B * EMB + 255) / 256, 256>>>(B);
    k_bidx     <<<(M + 255) / 256, 256>>>(si, M, B);
    k_prep     <<<EMB, XDIM>>>(W1);
    dim3 grid1((M + 127) / 128, 2);
    k_gemm1_mma<<<grid1, 512, SMEM_G1>>>(states, b1, out, M);
    k_segred   <<<(M + 255) / 256, 256>>>(out, M);
    k_mlp      <<<B, 256>>>(si, W2, b2);
    k_bcast    <<<(M * 64 + 255) / 256, 256>>>(out, M);

    long long need = (long long)M * OUTW + (long long)M;
    if ((long long)out_size >= need)
        k_tail<<<(M + 255) / 256, 256>>>(out, (size_t)M * OUTW, M);
}

// round 7
// speedup vs baseline: 3.0398x; 1.0821x over previous
#include <cuda_runtime.h>
#include <cuda_bf16.h>
#include <math.h>

#define DEV_DIM 192
#define PE_DIM  64
#define EMB     256
#define XDIM    256          // K of GEMM1
#define OUTW    512
#define MAXM    262144
#define MAXB    1024

// ===================== scratch (no allocations allowed) =====================
__device__ float g_sums[MAXB * EMB];
__device__ float g_maxs[MAXB * EMB];
__device__ float g_agg [MAXB * EMB];
__device__ float g_pos [MAXM];
__device__ int   g_bidx[MAXM];
__device__ __nv_bfloat16 g_wt_hi[EMB * XDIM];   // W1^T hi  [n][k]
__device__ __nv_bfloat16 g_wt_lo[EMB * XDIM];   // W1^T lo  [n][k]

// ===================== helpers =====================
__device__ __forceinline__ unsigned smem_u32(const void* p) {
    unsigned a;
    asm("{ .reg .u64 t; cvta.to.shared.u64 t, %1; cvt.u32.u64 %0, t; }" : "=r"(a) : "l"(p));
    return a;
}
__device__ __forceinline__ void cp_async16(unsigned dst, const void* src) {
    asm volatile("cp.async.cg.shared.global [%0], [%1], 16;" :: "r"(dst), "l"(src));
}
#define CP_ASYNC_COMMIT()   asm volatile("cp.async.commit_group;" ::: "memory")
#define CP_ASYNC_WAIT_ALL() asm volatile("cp.async.wait_group 0;" ::: "memory")

#define LDSM_X4(r0, r1, r2, r3, addr)                                          \
    asm volatile("ldmatrix.sync.aligned.m8n8.x4.shared.b16 {%0,%1,%2,%3}, [%4];" \
        : "=r"(r0), "=r"(r1), "=r"(r2), "=r"(r3) : "r"(addr))

__device__ __forceinline__ void mma_bf16(float* d, const unsigned* a, const unsigned* b) {
    asm volatile(
        "mma.sync.aligned.m16n8k16.row.col.f32.bf16.bf16.f32 "
        "{%0,%1,%2,%3}, {%4,%5,%6,%7}, {%8,%9}, {%0,%1,%2,%3};"
        : "+f"(d[0]), "+f"(d[1]), "+f"(d[2]), "+f"(d[3])
        : "r"(a[0]), "r"(a[1]), "r"(a[2]), "r"(a[3]), "r"(b[0]), "r"(b[1]));
}

__device__ __forceinline__ void atomicMaxF(float* addr, float v) {
    if (v >= 0.0f) atomicMax((int*)addr, __float_as_int(v));
    else           atomicMin((unsigned int*)addr, __float_as_uint(v));
}
__device__ __forceinline__ unsigned packbf2(float v0, float v1, float* r0, float* r1) {
    __nv_bfloat16 h0 = __float2bfloat16_rn(v0);
    __nv_bfloat16 h1 = __float2bfloat16_rn(v1);
    *r0 = v0 - __bfloat162float(h0);
    *r1 = v1 - __bfloat162float(h1);
    return ((unsigned)__bfloat16_as_ushort(h1) << 16) | (unsigned)__bfloat16_as_ushort(h0);
}
__device__ __forceinline__ unsigned packbf2_only(float v0, float v1) {
    return ((unsigned)__bfloat16_as_ushort(__float2bfloat16_rn(v1)) << 16)
         | (unsigned)__bfloat16_as_ushort(__float2bfloat16_rn(v0));
}

// ===================== kernel 0: init segment accumulators =====================
__global__ void k_init(int B) {
    int i = blockIdx.x * blockDim.x + threadIdx.x;
    if (i < B * EMB) {
        g_sums[i] = 0.0f;
        ((unsigned int*)g_maxs)[i] = 0xFF800000u;   // -inf
    }
}

// ===================== kernel 1: batch_index + 1-based position =====================
__global__ void k_bidx(const int* __restrict__ si, int M, int B) {
    int j = blockIdx.x * blockDim.x + threadIdx.x;
    if (j >= M) return;
    int lo = 1, hi = B + 1;
    while (lo < hi) {
        int mid = (lo + hi) >> 1;
        if (__ldg(si + mid) <= j) lo = mid + 1; else hi = mid;
    }
    int seg = lo - 1;
    g_bidx[j] = seg;
    g_pos[j]  = (float)(j - __ldg(si + seg) + 1);
}

// ===================== kernel 1b: W1 -> transposed bf16 hi/lo =====================
__global__ void k_prep(const float* __restrict__ W1) {
    int n = blockIdx.x;           // output col 0..255
    int k = threadIdx.x;          // k 0..255
    float w = __ldg(W1 + (size_t)k * EMB + n);
    __nv_bfloat16 h = __float2bfloat16_rn(w);
    g_wt_hi[n * XDIM + k] = h;
    g_wt_lo[n * XDIM + k] = __float2bfloat16_rn(w - __bfloat162float(h));
}

// ===================== kernel 2: bf16x3 HMMA GEMM1 via ldmatrix =====================
// CTA: 128 rows x 256 cols (FULL N), 256 threads (8 warps, warp tile 64x64).
// K=256 in 8 chunks of 32, double buffered. Chunks 0-5: states, 6-7: PE.
#define KC       32
#define NCHK     8
#define PA       40                     // smem pitch in bf16 (80 B)
#define A_BUF    10240                  // 128 * 80 B per matrix
#define B_BUF    20480                  // 256 * 80 B per matrix
#define A_TILE   1280                   // 16 * 80 B (one 16-row tile)
#define OFF_BIAS 0                      // 256 f32
#define OFF_INVF 1024                   // 32 f32
#define OFF_A    1280                   // [buf][AH | AL]
#define OFF_B    42240                  // [buf][BH | BL]
#define SMEM_G1  124160

__device__ __forceinline__ void stage_B(unsigned sb, int ck, int buf) {
    int tid = threadIdx.x;
    unsigned bh = sb + OFF_B + buf * (2 * B_BUF);
    unsigned bl = bh + B_BUF;
    const char* srcH = (const char*)(g_wt_hi) + ck * (KC * 2);
    const char* srcL = (const char*)(g_wt_lo) + ck * (KC * 2);
    // per matrix: 256 n-rows * 4 x 16B segments = 1024 txns; 256 threads -> 4 each
#pragma unroll
    for (int t = 0; t < 4; t++) {
        int i = tid + t * 256;
        int n = i >> 2, s = i & 3;
        unsigned d = (unsigned)(n * (PA * 2) + s * 16);
        cp_async16(bh + d, srcH + (size_t)n * (XDIM * 2) + s * 16);
        cp_async16(bl + d, srcL + (size_t)n * (XDIM * 2) + s * 16);
    }
}

__device__ __forceinline__ void load_A_vals(const float* __restrict__ states,
                                            float pos, const float* sinvf,
                                            int grow, int valid, int ck, float* v) {
    int kq = (threadIdx.x & 1) * 16;
    int kbase = ck * KC + kq;
    if (ck < 6) {                       // pure states
        if (valid) {
            const float4* p = (const float4*)(states + (size_t)grow * DEV_DIM + kbase);
#pragma unroll
            for (int q = 0; q < 4; q++) {
                float4 x = __ldg(p + q);
                v[q * 4 + 0] = x.x; v[q * 4 + 1] = x.y;
                v[q * 4 + 2] = x.z; v[q * 4 + 3] = x.w;
            }
        } else {
#pragma unroll
            for (int e = 0; e < 16; e++) v[e] = 0.0f;
        }
    } else {                            // pure PE (k 192..255)
        int c0 = kbase - DEV_DIM;       // 0/16/32/48
#pragma unroll
        for (int f = 0; f < 8; f++) {
            float ang = pos * sinvf[(c0 >> 1) + f];
            float kq2 = rintf(ang * 0.15915494309189535f);
            float rr = fmaf(kq2, -6.28125f, ang);
            rr = fmaf(kq2, -1.9353071795864769e-3f, rr);
            float s, c;
            __sincosf(rr, &s, &c);
            v[2 * f] = s; v[2 * f + 1] = c;
        }
    }
}

__device__ __forceinline__ void store_A(char* smem, int buf, const float* v) {
    int arow = threadIdx.x >> 1;
    int kq   = (threadIdx.x & 1) * 16;
    unsigned hi[8], lo[8];
#pragma unroll
    for (int q = 0; q < 8; q++) {
        float r0, r1;
        hi[q] = packbf2(v[2 * q], v[2 * q + 1], &r0, &r1);
        lo[q] = packbf2_only(r0, r1);
    }
    char* ah = smem + OFF_A + buf * (2 * A_BUF) + arow * (PA * 2) + kq * 2;
    char* al = ah + A_BUF;
    ((uint4*)ah)[0] = make_uint4(hi[0], hi[1], hi[2], hi[3]);
    ((uint4*)ah)[1] = make_uint4(hi[4], hi[5], hi[6], hi[7]);
    ((uint4*)al)[0] = make_uint4(lo[0], lo[1], lo[2], lo[3]);
    ((uint4*)al)[1] = make_uint4(lo[4], lo[5], lo[6], lo[7]);
}

__global__ __launch_bounds__(256, 1) void k_gemm1_mma(
    const float* __restrict__ states, const float* __restrict__ b1,
    float* __restrict__ out, int M)
{
    extern __shared__ char smem[];
    const unsigned sb = smem_u32(smem);
    const int tid  = threadIdx.x;
    const int wid  = tid >> 5;
    const int lane = tid & 31;
    const int g    = lane >> 2;
    const int tg   = lane & 3;
    const int wm   = wid >> 2;       // 0..1 (64 rows)
    const int wn   = wid & 3;        // 0..3 (64 cols)
    const int row0 = blockIdx.x * 128;

    float* sbias = (float*)(smem + OFF_BIAS);
    float* sinvf = (float*)(smem + OFF_INVF);

    if (tid < 256) sbias[tid] = __ldg(b1 + tid);
    if (tid < 32) {
        float lg = logf(10000.0f);
        sinvf[tid] = expf(-(lg * ((2.0f * (float)tid) / (float)PE_DIM)));
    }
    __syncthreads();

    const int arow  = tid >> 1;
    const int grow  = row0 + arow;
    const int valid = (grow < M);
    const float pos = valid ? __ldg(&g_pos[grow]) : 1.0f;

    // ldmatrix per-lane base offsets
    const int g4 = lane >> 3;           // 0..3
    const int lr = lane & 7;
    const unsigned a_off = (unsigned)((wm * 64 + (g4 & 1) * 8 + lr) * (PA * 2)) + (g4 >> 1) * 16;
    const unsigned b_off = (unsigned)((wn * 64 + (g4 >> 1) * 8 + lr) * (PA * 2)) + (g4 & 1) * 16;

    // ---- prologue: chunk 0 ----
    stage_B(sb, 0, 0);
    CP_ASYNC_COMMIT();
    {
        float v[16];
        load_A_vals(states, pos, sinvf, grow, valid, 0, v);
        store_A(smem, 0, v);
    }
    CP_ASYNC_WAIT_ALL();
    __syncthreads();

    float acc[4][8][4];
#pragma unroll
    for (int i = 0; i < 4; i++)
#pragma unroll
        for (int j = 0; j < 8; j++)
#pragma unroll
            for (int e = 0; e < 4; e++) acc[i][j][e] = 0.0f;

#pragma unroll 1
    for (int c = 0; c < NCHK; c++) {
        const int buf = c & 1;
        float vnext[16];
        const bool more = (c < NCHK - 1);
        if (more) {
            stage_B(sb, c + 1, buf ^ 1);
            CP_ASYNC_COMMIT();
            load_A_vals(states, pos, sinvf, grow, valid, c + 1, vnext);
        }

        const unsigned sAH = sb + OFF_A + buf * (2 * A_BUF);
        const unsigned sAL = sAH + A_BUF;
        const unsigned sBH = sb + OFF_B + buf * (2 * B_BUF);
        const unsigned sBL = sBH + B_BUF;

#pragma unroll
        for (int ks = 0; ks < 2; ks++) {
            const unsigned kb = ks * 32;            // 16 k * 2 B
            unsigned ah[4][4], al[4][4];
#pragma unroll
            for (int i = 0; i < 4; i++) {
                LDSM_X4(ah[i][0], ah[i][1], ah[i][2], ah[i][3],
                        sAH + a_off + i * A_TILE + kb);
                LDSM_X4(al[i][0], al[i][1], al[i][2], al[i][3],
                        sAL + a_off + i * A_TILE + kb);
            }
#pragma unroll
            for (int jj = 0; jj < 4; jj++) {
                unsigned bh[2][2], bl[2][2];
                LDSM_X4(bh[0][0], bh[0][1], bh[1][0], bh[1][1],
                        sBH + b_off + jj * A_TILE + kb);
                LDSM_X4(bl[0][0], bl[0][1], bl[1][0], bl[1][1],
                        sBL + b_off + jj * A_TILE + kb);
#pragma unroll
                for (int i = 0; i < 4; i++) {
#pragma unroll
                    for (int p = 0; p < 2; p++) {
                        mma_bf16(acc[i][2 * jj + p], ah[i], bh[p]);
                        mma_bf16(acc[i][2 * jj + p], ah[i], bl[p]);
                        mma_bf16(acc[i][2 * jj + p], al[i], bh[p]);
                    }
                }
            }
        }

        if (more) {
            store_A(smem, buf ^ 1, vnext);
            CP_ASYNC_WAIT_ALL();
            __syncthreads();
        }
    }

    // ---- epilogue: bias + LeakyReLU, store out[:, 0:256) ----
#pragma unroll
    for (int i = 0; i < 4; i++) {
        int ra = row0 + wm * 64 + i * 16 + g;
#pragma unroll
        for (int h = 0; h < 2; h++) {
            int row = ra + h * 8;
            if (row < M) {
                float* op = out + (size_t)row * OUTW + wn * 64;
#pragma unroll
                for (int j = 0; j < 8; j++) {
                    int ccol = j * 8 + tg * 2;
                    float x0 = acc[i][j][h * 2 + 0] + sbias[wn * 64 + ccol];
                    float x1 = acc[i][j][h * 2 + 1] + sbias[wn * 64 + ccol + 1];
                    x0 = (x0 >= 0.0f) ? x0 : 0.01f * x0;
                    x1 = (x1 >= 0.0f) ? x1 : 0.01f * x1;
                    *(float2*)(op + ccol) = make_float2(x0, x1);
                }
            }
        }
    }
}

// ===================== kernel 3: ragged segment sum + max (prefetched) =====================
__global__ __launch_bounds__(256) void k_segred(const float* __restrict__ out, int M) {
    __shared__ int sseg[256];
    int c = threadIdx.x;
    int row0 = blockIdx.x * 256;
    int rows = min(256, M - row0);
    sseg[c] = __ldg(&g_bidx[row0 + min(c, rows - 1)]);
    __syncthreads();
    const float* p = out + (size_t)row0 * OUTW + c;
    float v[8];
#pragma unroll
    for (int i = 0; i < 8; i++)
        v[i] = (i < rows) ? __ldg(p + (size_t)i * OUTW) : 0.0f;
    float sum = 0.0f, mx = __int_as_float(0xFF800000);
    int cur = sseg[0];
#pragma unroll 8
    for (int r = 0; r < 256; r++) {
        if (r >= rows) break;
        float val = v[r & 7];
        if (r + 8 < rows) v[r & 7] = __ldg(p + (size_t)(r + 8) * OUTW);
        int seg = sseg[r];
        if (seg != cur) {
            atomicAdd(&g_sums[cur * EMB + c], sum);
            atomicMaxF(&g_maxs[cur * EMB + c], mx);
            sum = 0.0f; mx = __int_as_float(0xFF800000); cur = seg;
        }
        sum += val;
        mx = fmaxf(mx, val);
    }
    atomicAdd(&g_sums[cur * EMB + c], sum);
    atomicMaxF(&g_maxs[cur * EMB + c], mx);
}

// ===================== kernel 4: agg = leaky(concat(mean,max) @ W2 + b2) =====================
__global__ __launch_bounds__(256) void k_mlp(const int* __restrict__ si,
                                             const float* __restrict__ W2,
                                             const float* __restrict__ b2) {
    __shared__ float vec[2 * EMB];
    __shared__ float par[4][EMB];
    int s = blockIdx.x, t = threadIdx.x;
    int cnt = __ldg(si + s + 1) - __ldg(si + s);
    float inv = (cnt > 0) ? (1.0f / (float)cnt) : 1.0f;
    vec[t]       = g_sums[s * EMB + t] * inv;
    vec[EMB + t] = (cnt > 0) ? g_maxs[s * EMB + t] : 0.0f;
    __syncthreads();
    int tq = t >> 6;
    int tc = (t & 63) * 4;
    float a0 = 0.f, a1 = 0.f, a2 = 0.f, a3 = 0.f;
#pragma unroll 4
    for (int k = tq * 128; k < tq * 128 + 128; k++) {
        float vk = vec[k];
        float4 w = __ldg((const float4*)(W2 + (size_t)k * EMB + tc));
        a0 = fmaf(vk, w.x, a0); a1 = fmaf(vk, w.y, a1);
        a2 = fmaf(vk, w.z, a2); a3 = fmaf(vk, w.w, a3);
    }
    par[tq][tc] = a0; par[tq][tc + 1] = a1; par[tq][tc + 2] = a2; par[tq][tc + 3] = a3;
    __syncthreads();
    if (tq == 0) {
#pragma unroll
        for (int e = 0; e < 4; e++) {
            int cc = tc + e;
            float acc = par[0][cc] + par[1][cc] + par[2][cc] + par[3][cc] + __ldg(b2 + cc);
            acc = (acc >= 0.0f) ? acc : 0.01f * acc;
            g_agg[s * EMB + cc] = acc;
        }
    }
}

// ===================== kernel 5: broadcast agg into out[:, 256:512] =====================
__global__ __launch_bounds__(256) void k_bcast(float* __restrict__ out, int M) {
    int idx = blockIdx.x * blockDim.x + threadIdx.x;
    int row = idx >> 6;
    int q   = idx & 63;
    if (row >= M) return;
    int seg = __ldg(&g_bidx[row]);
    float4 v = __ldg((const float4*)(g_agg + (size_t)seg * EMB) + q);
    *((float4*)(out + (size_t)row * OUTW + EMB) + q) = v;
}

// ===================== kernel 6 (optional): second tuple output (batch_index) =====================
__global__ void k_tail(float* __restrict__ out, size_t off, int M) {
    int j = blockIdx.x * blockDim.x + threadIdx.x;
    if (j < M) out[off + j] = (float)g_bidx[j];
}

// ===================== launch =====================
extern "C" void kernel_launch(void* const* d_in, const int* in_sizes, int n_in,
                              void* d_out, int out_size) {
    const float* states = (const float*)d_in[0];
    const int*   si     = (const int*)  d_in[1];
    const float* W1     = (const float*)d_in[2];
    const float* b1     = (const float*)d_in[3];
    const float* W2     = (const float*)d_in[4];
    const float* b2     = (const float*)d_in[5];
    float* out = (float*)d_out;

    int M = in_sizes[0] / DEV_DIM;
    int B = in_sizes[1] - 1;
    if (M > MAXM) M = MAXM;
    if (B > MAXB) B = MAXB;

    cudaFuncSetAttribute(k_gemm1_mma, cudaFuncAttributeMaxDynamicSharedMemorySize, SMEM_G1);

    k_init     <<<(B * EMB + 255) / 256, 256>>>(B);
    k_bidx     <<<(M + 255) / 256, 256>>>(si, M, B);
    k_prep     <<<EMB, XDIM>>>(W1);
    k_gemm1_mma<<<(M + 127) / 128, 256, SMEM_G1>>>(states, b1, out, M);
    k_segred   <<<(M + 255) / 256, 256>>>(out, M);
    k_mlp      <<<B, 256>>>(si, W2, b2);
    k_bcast    <<<(M * 64 + 255) / 256, 256>>>(out, M);

    long long need = (long long)M * OUTW + (long long)M;
    if ((long long)out_size >= need)
        k_tail<<<(M + 255) / 256, 256>>>(out, (size_t)M * OUTW, M);
}